// round 17
// baseline (speedup 1.0000x reference)
#include <cuda_runtime.h>
#include <cuda_bf16.h>
#include <cstdint>

#define IMG   128
#define CDIM  256
#define HDS   8
#define HD    32
#define NELEM 33554432   // 131072 * 256

// Scratch (allocation-free rule: device globals)
__device__ float g_v[NELEM];        // v buffer fp32
__device__ float g_o[NELEM];        // agg output (tf32-rounded)
__device__ float g_wv32[65536];     // Wv rounded to tf32
__device__ float g_wp32[65536];     // Wp rounded to tf32

// ---------------------------------------------------------------------------
// helpers
// ---------------------------------------------------------------------------
__device__ __forceinline__ uint32_t smem_u32(const void* p) {
    uint32_t a;
    asm("{ .reg .u64 t; cvta.to.shared.u64 t, %1; cvt.u32.u64 %0, t; }"
        : "=r"(a) : "l"(p));
    return a;
}
__device__ __forceinline__ void cp16(uint32_t saddr, const void* g) {
    asm volatile("cp.async.cg.shared.global [%0], [%1], 16;"
                 :: "r"(saddr), "l"(g));
}
__device__ __forceinline__ void cp4(uint32_t saddr, const void* g) {
    asm volatile("cp.async.ca.shared.global [%0], [%1], 4;"
                 :: "r"(saddr), "l"(g));
}
__device__ __forceinline__ void ldm_x4(uint32_t* d, uint32_t a) {
    asm volatile("ldmatrix.sync.aligned.m8n8.x4.shared.b16 {%0,%1,%2,%3}, [%4];"
                 : "=r"(d[0]), "=r"(d[1]), "=r"(d[2]), "=r"(d[3]) : "r"(a));
}
__device__ __forceinline__ void cvt_tf32(uint32_t& x) {
    asm("cvt.rna.tf32.f32 %0, %0;" : "+r"(x));
}
__device__ __forceinline__ void mma_tf32(float* c, const uint32_t* a, const uint32_t* b) {
    asm volatile("mma.sync.aligned.m16n8k8.row.col.f32.tf32.tf32.f32 "
                 "{%0,%1,%2,%3}, {%4,%5,%6,%7}, {%8,%9}, {%0,%1,%2,%3};"
                 : "+f"(c[0]), "+f"(c[1]), "+f"(c[2]), "+f"(c[3])
                 : "r"(a[0]), "r"(a[1]), "r"(a[2]), "r"(a[3]),
                   "r"(b[0]), "r"(b[1]));
}

// ---------------------------------------------------------------------------
// W round: fp32 -> tf32 (RNA), both weight matrices
// ---------------------------------------------------------------------------
__global__ void round_w_kernel(const float* __restrict__ W1, float* __restrict__ O1,
                               const float* __restrict__ W2, float* __restrict__ O2)
{
    int i = blockIdx.x * 256 + threadIdx.x;
    uint32_t a = __float_as_uint(W1[i]);
    cvt_tf32(a);
    O1[i] = __uint_as_float(a);
    uint32_t b = __float_as_uint(W2[i]);
    cvt_tf32(b);
    O2[i] = __uint_as_float(b);
}

// ---------------------------------------------------------------------------
// TF32 GEMM: C[M,256] = A[M,256] @ W[256,256]^T + bias
//  CTA tile 128x64, 8 warps (4M x 2N), warp tile 32x32, 3 CTAs/SM.
//  3-stage cp.async pipeline, BK=32 (4 k8 steps/chunk), SW128 swizzle,
//  ldmatrix-on-fp32 fragments. DO_CVT: round A fragments to tf32 in-register
//  (GEMM1); GEMM2's A is pre-rounded by the agg kernel -> no cvt.
//  GRID = (4, 1024): the four CTAs sharing an A-tile are launch-adjacent,
//  so 3 of the 4 A passes hit L2.
// Stage: A(16384) | B(8192) = 24576 B; 3 stages = 73728 -> 3 CTAs/SM.
// ---------------------------------------------------------------------------
#define NCHUNK 8
#define ROWB   128
#define OFF_A  0
#define OFF_B  16384
#define STAGEB 24576
#define GM_SMEM (3 * STAGEB)       // 73728

__device__ __forceinline__ uint32_t swz(int r, int seg) {
    return (uint32_t)(r * ROWB) + (uint32_t)((seg ^ (r & 7)) << 4);
}

template <bool DO_CVT>
__global__ void __launch_bounds__(256, 3)
gemm_tf32_kernel(const float* __restrict__ A_g,
                 const float* __restrict__ B_g,
                 const float* __restrict__ bias,
                 float* __restrict__ C)
{
    extern __shared__ char sm[];
    const uint32_t sb = smem_u32(sm);
    const int tid  = threadIdx.x;
    const int wid  = tid >> 5, lane = tid & 31;
    const int bm   = blockIdx.y * 128;       // M from grid.y (1024)
    const int bn   = blockIdx.x * 64;        // N from grid.x (4)
    const int m0   = (wid & 3) * 32;
    const int n0   = (wid >> 2) * 32;

    const int a_row  = lane & 15;
    const int a_segl = lane >> 4;
    const int b_row  = (lane & 7) + (lane >> 4) * 8;
    const int b_segl = (lane >> 3) & 1;
    const uint32_t lane_xor = (uint32_t)(lane & 7);

    auto load_chunk = [&](int kc, int st) {
        // A: 1024 granules -> 4 per thread
#pragma unroll
        for (int s = 0; s < 4; s++) {
            const int idx = tid + s * 256;
            const int r = idx >> 3, seg = idx & 7;
            const uint32_t so = (uint32_t)(st * STAGEB) + swz(r, seg);
            cp16(sb + so + OFF_A,
                 A_g + (size_t)(bm + r) * 256 + kc * 32 + seg * 4);
        }
        // B: 512 granules -> 2 per thread
#pragma unroll
        for (int s = 0; s < 2; s++) {
            const int idx = tid + s * 256;
            const int r = idx >> 3, seg = idx & 7;
            const uint32_t so = (uint32_t)(st * STAGEB) + swz(r, seg);
            cp16(sb + so + OFF_B,
                 B_g + (size_t)(bn + r) * 256 + kc * 32 + seg * 4);
        }
    };

    float acc[2][4][4];
#pragma unroll
    for (int mt = 0; mt < 2; mt++)
#pragma unroll
        for (int nt = 0; nt < 4; nt++)
#pragma unroll
            for (int q = 0; q < 4; q++) acc[mt][nt][q] = 0.f;

    load_chunk(0, 0);
    asm volatile("cp.async.commit_group;" ::: "memory");
    load_chunk(1, 1);
    asm volatile("cp.async.commit_group;" ::: "memory");

    int sr = 0, sw = 2;
    for (int kc = 0; kc < NCHUNK; kc++) {
        asm volatile("cp.async.wait_group 1;" ::: "memory");
        __syncthreads();
        if (kc + 2 < NCHUNK) {
            load_chunk(kc + 2, sw);
            if (++sw == 3) sw = 0;
        }
        asm volatile("cp.async.commit_group;" ::: "memory");

        const uint32_t stb = sb + (uint32_t)(sr * STAGEB);
#pragma unroll
        for (int k8 = 0; k8 < 4; k8++) {
            const uint32_t a_soff = (uint32_t)(((k8 * 2 + a_segl) ^ lane_xor) << 4);
            const uint32_t b_soff = (uint32_t)(((k8 * 2 + b_segl) ^ lane_xor) << 4);
            uint32_t AF[2][4];
#pragma unroll
            for (int mt = 0; mt < 2; mt++) {
                const uint32_t aaddr = stb + OFF_A
                    + (uint32_t)((m0 + mt * 16 + a_row) * ROWB) + a_soff;
                ldm_x4(AF[mt], aaddr);
                if (DO_CVT) {
                    cvt_tf32(AF[mt][0]); cvt_tf32(AF[mt][1]);
                    cvt_tf32(AF[mt][2]); cvt_tf32(AF[mt][3]);
                }
            }
#pragma unroll
            for (int np = 0; np < 2; np++) {
                const uint32_t baddr = stb + OFF_B
                    + (uint32_t)((n0 + np * 16 + b_row) * ROWB) + b_soff;
                uint32_t bf[4];
                ldm_x4(bf, baddr);
                const int nt0 = 2 * np, nt1 = 2 * np + 1;
                mma_tf32(acc[0][nt0], AF[0], bf + 0);
                mma_tf32(acc[1][nt0], AF[1], bf + 0);
                mma_tf32(acc[0][nt1], AF[0], bf + 2);
                mma_tf32(acc[1][nt1], AF[1], bf + 2);
            }
        }
        if (++sr == 3) sr = 0;
    }

#pragma unroll
    for (int mt = 0; mt < 2; mt++) {
        const int row = bm + m0 + mt * 16 + (lane >> 2);
#pragma unroll
        for (int nt = 0; nt < 4; nt++) {
            const int col = bn + n0 + nt * 8 + 2 * (lane & 3);
            const float b0 = __ldg(bias + col), b1 = __ldg(bias + col + 1);
            float2 v0, v1;
            v0.x = acc[mt][nt][0] + b0; v0.y = acc[mt][nt][1] + b1;
            v1.x = acc[mt][nt][2] + b0; v1.y = acc[mt][nt][3] + b1;
            *reinterpret_cast<float2*>(C + (size_t)row * 256 + col) = v0;
            *reinterpret_cast<float2*>(C + (size_t)(row + 8) * 256 + col) = v1;
        }
    }
}

// ---------------------------------------------------------------------------
// Neighborhood aggregation: 8x16 strips, 3 CTAs/SM, cp.async staging,
// rolling 7x7 register window. Output pre-rounded to tf32 (feeds GEMM2).
// ---------------------------------------------------------------------------
#define AGTILE 16
#define STRIPR 8
#define NRMAX  14
#define HALO   22
#define WPAD   52
#define VS_FLOATS (NRMAX * HALO * HD)             // 9856
#define WS_FLOATS (128 * WPAD)                    // 6656
#define AGG_SMEM  ((VS_FLOATS + WS_FLOATS) * 4)   // 66048

__device__ __forceinline__ constexpr int shifts_fn(int CLS, int tj) {
    return CLS == 0 ? (tj > 3 ? tj - 3 : 0)
         : CLS == 1 ? tj
         : (tj < 12 ? tj : 12);
}

template <int CLS>
__device__ __forceinline__ void agg_row(
    const float* __restrict__ vs, const float* __restrict__ ws,
    int i0, int j0, int rs, int ti,
    int warp, int lane, int b, int head,
    float* __restrict__ o)
{
    const int i  = i0 + ti;
    const int si = min(max(i - 3, 0), IMG - 7) - rs;
    const float* vrow = vs + si * (HALO * HD) + lane;

    float v[7][7];
#pragma unroll
    for (int ki = 0; ki < 7; ki++)
#pragma unroll
        for (int kj = 0; kj < 7; kj++)
            v[ki][kj] = vrow[(ki * HALO + kj) * HD];

#pragma unroll
    for (int tj = 0; tj < AGTILE; tj++) {
        const int sh = shifts_fn(CLS, tj);
        if (tj > 0 && sh != shifts_fn(CLS, tj - 1)) {
            const int c = sh + 6;
            const int slot = c % 7;
#pragma unroll
            for (int ki = 0; ki < 7; ki++)
                v[ki][slot] = vrow[(ki * HALO + c) * HD];
        }

        const int pl = warp * AGTILE + tj;
        const float4* wq = reinterpret_cast<const float4*>(ws + pl * WPAD);
        float a0 = 0.f, a1 = 0.f, a2 = 0.f, a3 = 0.f;
#pragma unroll
        for (int q = 0; q < 13; q++) {
            const float4 wv = wq[q];
#pragma unroll
            for (int e = 0; e < 4; e++) {
                const int idx = q * 4 + e;
                if (idx < 49) {
                    const int ki = idx / 7, kj = idx % 7;
                    const float we = (e == 0) ? wv.x : (e == 1) ? wv.y
                                   : (e == 2) ? wv.z : wv.w;
                    const float vv = v[ki][(sh + kj) % 7];
                    if (e == 0)      a0 += we * vv;
                    else if (e == 1) a1 += we * vv;
                    else if (e == 2) a2 += we * vv;
                    else             a3 += we * vv;
                }
            }
        }
        const float acc = (a0 + a1) + (a2 + a3);

        uint32_t accb = __float_as_uint(acc);
        cvt_tf32(accb);                          // pre-round for GEMM2

        const int j = j0 + tj;
        o[(((size_t)b * IMG + i) * IMG + j) * CDIM + head * HD + lane]
            = __uint_as_float(accb);
    }
}

__global__ void __launch_bounds__(256, 3)
agg_kernel(const float* __restrict__ v,
           const float* __restrict__ attn,
           float* __restrict__ o)
{
    const int st  = blockIdx.x >> 3;
    const int jt  = blockIdx.x & 7;
    const int head = blockIdx.y;
    const int b    = blockIdx.z;
    const int i0 = st * STRIPR;
    const int j0 = jt * AGTILE;

    const int rs = min(max(i0 - 3, 0), IMG - 7);
    const int re = min(max(i0 + STRIPR - 4, 0), IMG - 7) + 6;
    const int cs = min(max(j0 - 3, 0), IMG - 7);
    const int ce = min(max(j0 + AGTILE - 4, 0), IMG - 7) + 6;
    const int nr = re - rs + 1;            // <= 14
    const int nc = ce - cs + 1;            // <= 22

    extern __shared__ float sm_f[];
    float* vs = sm_f;
    float* ws = sm_f + VS_FLOATS;
    const uint32_t sb = smem_u32(sm_f);

    const int tid = threadIdx.x;
    const int warp = tid >> 5;
    const int lane = tid & 31;

    const float* vbase = v + (size_t)b * IMG * IMG * CDIM + head * HD;
    const int nquads = nr * nc * (HD / 4);
    for (int idx = tid; idx < nquads; idx += 256) {
        const int d4 = idx & 7;
        const int p  = idx >> 3;
        const int rr = p / nc;
        const int cc = p - rr * nc;
        cp16(sb + (uint32_t)(((rr * HALO + cc) * HD + d4 * 4) * 4),
             vbase + ((size_t)(rs + rr) * IMG + (cs + cc)) * CDIM + d4 * 4);
    }

    const float* abase = attn + ((((size_t)b * HDS + head) * IMG + i0) * IMG + j0) * 49;
    const uint32_t wsb = sb + (uint32_t)(VS_FLOATS * 4);
    for (int idx = tid; idx < 128 * 49; idx += 256) {
        const int pl = idx / 49;
        const int k  = idx - pl * 49;
        const int ti = pl >> 4;
        const int tj = pl & 15;
        cp4(wsb + (uint32_t)((pl * WPAD + k) * 4),
            abase + ((size_t)ti * IMG + tj) * 49 + k);
    }
    asm volatile("cp.async.commit_group;" ::: "memory");
    asm volatile("cp.async.wait_group 0;" ::: "memory");
    __syncthreads();

    if (j0 == 0)
        agg_row<0>(vs, ws, i0, j0, rs, warp, warp, lane, b, head, o);
    else if (j0 == IMG - AGTILE)
        agg_row<2>(vs, ws, i0, j0, rs, warp, warp, lane, b, head, o);
    else
        agg_row<1>(vs, ws, i0, j0, rs, warp, warp, lane, b, head, o);
}

// ---------------------------------------------------------------------------
extern "C" void kernel_launch(void* const* d_in, const int* in_sizes, int n_in,
                              void* d_out, int out_size)
{
    const float* x    = (const float*)d_in[0];
    const float* attn = (const float*)d_in[1];
    const float* Wv   = (const float*)d_in[2];
    const float* bv   = (const float*)d_in[3];
    const float* Wp   = (const float*)d_in[4];
    const float* bp   = (const float*)d_in[5];
    float*       out  = (float*)d_out;

    void *pv, *po, *pwv, *pwp;
    cudaGetSymbolAddress(&pv,  g_v);
    cudaGetSymbolAddress(&po,  g_o);
    cudaGetSymbolAddress(&pwv, g_wv32);
    cudaGetSymbolAddress(&pwp, g_wp32);

    cudaFuncSetAttribute(gemm_tf32_kernel<true>,
                         cudaFuncAttributeMaxDynamicSharedMemorySize, GM_SMEM);
    cudaFuncSetAttribute(gemm_tf32_kernel<false>,
                         cudaFuncAttributeMaxDynamicSharedMemorySize, GM_SMEM);
    cudaFuncSetAttribute(agg_kernel,
                         cudaFuncAttributeMaxDynamicSharedMemorySize, AGG_SMEM);

    round_w_kernel<<<256, 256>>>(Wv, (float*)pwv, Wp, (float*)pwp);

    dim3 ggrid(4, 1024);     // bn fastest -> A-sharing CTAs co-scheduled
    gemm_tf32_kernel<true><<<ggrid, 256, GM_SMEM>>>(x, (float*)pwv, bv, (float*)pv);

    dim3 agrid(128, HDS, 8);
    agg_kernel<<<agrid, 256, AGG_SMEM>>>((float*)pv, attn, (float*)po);

    gemm_tf32_kernel<false><<<ggrid, 256, GM_SMEM>>>((float*)po, (float*)pwp, bp, out);
}